// round 9
// baseline (speedup 1.0000x reference)
#include <cuda_runtime.h>
#include <cstdint>

// RationalsModel: out[i] = P(x[i]) / (|x[i] * Q(x[i])| + 1)
//   P = sum_{p=0}^{63} coef[p]      * x^p
//   Q = sum_{p=0}^{63} coef[64 + p] * x^p
//
// R9: hardware model from R7/R8 evidence: fma pipe = 32 lanes/cyc shared,
// FFMA2 limited to 1 per 3 cyc (64-bit collector) -> pipe 67% busy, 1/3 idle.
// Scalar FFMA has a SEPARATE 32-bit collector limit (1 per 2 cyc).
// Mixed stream: per step 4x FFMA2 (4 elems) + 8x FFMA (4 elems) = 16
// pipe-lanes-cycles per 16 cycles = 100% pipe -> 2.0 cyc/elem vs 3.0.
// Staging identical to R7 (pack kernel -> constant memcpy -> LDCU).

__device__ __forceinline__ uint64_t pack2(float lo, float hi) {
    uint64_t r;
    asm("mov.b64 %0, {%1, %2};" : "=l"(r) : "f"(lo), "f"(hi));
    return r;
}

__device__ __forceinline__ void unpack2(uint64_t v, float& lo, float& hi) {
    asm("mov.b64 {%0, %1}, %2;" : "=f"(lo), "=f"(hi) : "l"(v));
}

// d = a * b + c  (packed 2x f32)
__device__ __forceinline__ uint64_t fma2(uint64_t a, uint64_t b, uint64_t c) {
    uint64_t d;
    asm("fma.rn.f32x2 %0, %1, %2, %3;" : "=l"(d) : "l"(a), "l"(b), "l"(c));
    return d;
}

// cC[p]    = dup2(coef[p])      (numerator)
// cC[64+p] = dup2(coef[64+p])   (denominator)
// Float view: ((const float*)cC)[2*p] = coef[p].
__constant__ uint64_t cC[128];
__device__ uint64_t g_pairs[128];

__global__ void pack_kernel(const float* __restrict__ coef) {
    int i = threadIdx.x;  // 128 threads
    uint32_t u = __float_as_uint(coef[i]);
    g_pairs[i] = (uint64_t)u | ((uint64_t)u << 32);
}

static constexpr int THREADS = 128;
static constexpr int ELEMS_PER_THREAD = 8;   // 4 packed (2 x f32x2) + 4 scalar
static constexpr int ELEMS_PER_BLOCK = THREADS * ELEMS_PER_THREAD;  // 1024
static constexpr int F4_PER_BLOCK = ELEMS_PER_BLOCK / 4;            // 256

__global__ __launch_bounds__(THREADS)
void rational_kernel(const float4* __restrict__ x4,
                     float4* __restrict__ out4)
{
    int tid = threadIdx.x;
    const float* cf = reinterpret_cast<const float*>(cC);

    int base = blockIdx.x * F4_PER_BLOCK + tid;
    float4 a = x4[base];             // -> packed lanes
    float4 b = x4[base + THREADS];   // -> scalar lanes

    // Packed state (4 elements in 2 f32x2 lanes)
    uint64_t xp0 = pack2(a.x, a.y);
    uint64_t xp1 = pack2(a.z, a.w);
    uint64_t pN0, pN1, pD0, pD1;
    {
        uint64_t n63 = cC[63];
        uint64_t m63 = cC[127];
        pN0 = n63; pN1 = n63;
        pD0 = m63; pD1 = m63;
    }

    // Scalar state (4 elements)
    float xs0 = b.x, xs1 = b.y, xs2 = b.z, xs3 = b.w;
    float n63f = cf[126];   // coef[63]
    float m63f = cf[254];   // coef[127]
    float sN0 = n63f, sN1 = n63f, sN2 = n63f, sN3 = n63f;
    float sD0 = m63f, sD1 = m63f, sD2 = m63f, sD3 = m63f;

    // Dual Horner, fully unrolled: per step 4 FFMA2 + 8 FFMA.
#pragma unroll
    for (int p = 62; p >= 0; p--) {
        uint64_t cn64 = cC[p];
        uint64_t cm64 = cC[64 + p];
        float cnf = cf[2 * p];
        float cmf = cf[128 + 2 * p];

        pN0 = fma2(pN0, xp0, cn64);
        pN1 = fma2(pN1, xp1, cn64);
        pD0 = fma2(pD0, xp0, cm64);
        pD1 = fma2(pD1, xp1, cm64);

        sN0 = fmaf(sN0, xs0, cnf);
        sN1 = fmaf(sN1, xs1, cnf);
        sN2 = fmaf(sN2, xs2, cnf);
        sN3 = fmaf(sN3, xs3, cnf);
        sD0 = fmaf(sD0, xs0, cmf);
        sD1 = fmaf(sD1, xs1, cmf);
        sD2 = fmaf(sD2, xs2, cmf);
        sD3 = fmaf(sD3, xs3, cmf);
    }

    // Epilogue: den = x * Q(x); out = P / (|den| + 1).
    float4 oa, ob;
    {
        float nlo, nhi, dlo, dhi, xlo, xhi;
        unpack2(pN0, nlo, nhi);
        unpack2(pD0, dlo, dhi);
        unpack2(xp0, xlo, xhi);
        oa.x = __fdividef(nlo, fabsf(xlo * dlo) + 1.0f);
        oa.y = __fdividef(nhi, fabsf(xhi * dhi) + 1.0f);
        unpack2(pN1, nlo, nhi);
        unpack2(pD1, dlo, dhi);
        unpack2(xp1, xlo, xhi);
        oa.z = __fdividef(nlo, fabsf(xlo * dlo) + 1.0f);
        oa.w = __fdividef(nhi, fabsf(xhi * dhi) + 1.0f);
    }
    ob.x = __fdividef(sN0, fabsf(xs0 * sD0) + 1.0f);
    ob.y = __fdividef(sN1, fabsf(xs1 * sD1) + 1.0f);
    ob.z = __fdividef(sN2, fabsf(xs2 * sD2) + 1.0f);
    ob.w = __fdividef(sN3, fabsf(xs3 * sD3) + 1.0f);

    out4[base] = oa;
    out4[base + THREADS] = ob;
}

extern "C" void kernel_launch(void* const* d_in, const int* in_sizes, int n_in,
                              void* d_out, int out_size) {
    const float* x    = (const float*)d_in[0];
    const float* coef = (const float*)d_in[1];
    float* out        = (float*)d_out;

    int N = in_sizes[0];                 // 4194304, divisible by 1024
    int blocks = N / ELEMS_PER_BLOCK;    // 4096

    // 1) Duplicate each coefficient into both halves of a u64 pair.
    pack_kernel<<<1, 128>>>(coef);

    // 2) Stage the packed pairs into constant memory (D2D memcpy node).
    void* src = nullptr;
    cudaGetSymbolAddress(&src, g_pairs);
    cudaMemcpyToSymbolAsync(cC, src, 128 * sizeof(uint64_t), 0,
                            cudaMemcpyDeviceToDevice, 0);

    // 3) Main compute kernel: mixed FFMA2 + FFMA stream.
    rational_kernel<<<blocks, THREADS>>>(
        (const float4*)x, (float4*)out);
}